// round 8
// baseline (speedup 1.0000x reference)
#include <cuda_runtime.h>
#include <math.h>

// Problem constants
#define Bq  4
#define Sq  1024
#define Dm  1024
#define NHh 16
#define DHh 64
#define DIf 4096
#define EPS 1e-5f

// ---------------- scratch (static device globals; no allocations) ----------
__device__ float g_k [Bq*Sq*Dm];
__device__ float g_v [Bq*Sq*Dm];
__device__ float g_r [Bq*Sq*Dm];
__device__ float g_qw[Bq*Sq*Dm];
__device__ float g_qr[Bq*Sq*Dm];
__device__ float g_av[Bq*Sq*Dm];
__device__ float g_ao[Bq*Sq*Dm];
__device__ float g_x [Bq*Sq*Dm];
__device__ float g_xr[Bq*Sq*Dm];
__device__ float g_h [Bq*Sq*DIf];
__device__ float g_f [Bq*Sq*Dm];
// tf32-rounded copies of inputs
__device__ float g_wr [Bq*Sq*Dm];
__device__ float g_rr2[Bq*Sq*Dm];
__device__ float g_Wqr[Dm*Dm];
__device__ float g_Wkr[Dm*Dm];
__device__ float g_Wvr[Dm*Dm];
__device__ float g_Wrr[Dm*Dm];
__device__ float g_Wor[Dm*Dm];
__device__ float g_W1r[Dm*DIf];
__device__ float g_W2r[DIf*Dm];

// ---------------- tf32 / mma / ldmatrix / cp.async helpers ------------------
__device__ __forceinline__ unsigned f2tf(float v) {
    unsigned r;
    asm("cvt.rna.tf32.f32 %0, %1;" : "=r"(r) : "f"(v));
    return r;
}
__device__ __forceinline__ float roundtf(float v) { return __uint_as_float(f2tf(v)); }

__device__ __forceinline__ void mma_tf32(float* d, const uint4& a, const uint2& b) {
    asm volatile(
        "mma.sync.aligned.m16n8k8.row.col.f32.tf32.tf32.f32 "
        "{%0,%1,%2,%3}, {%4,%5,%6,%7}, {%8,%9}, {%0,%1,%2,%3};"
        : "+f"(d[0]), "+f"(d[1]), "+f"(d[2]), "+f"(d[3])
        : "r"(a.x), "r"(a.y), "r"(a.z), "r"(a.w), "r"(b.x), "r"(b.y));
}

__device__ __forceinline__ uint4 ldsm4(unsigned addr) {
    uint4 d;
    asm volatile("ldmatrix.sync.aligned.m8n8.x4.shared.b16 {%0,%1,%2,%3}, [%4];"
                 : "=r"(d.x), "=r"(d.y), "=r"(d.z), "=r"(d.w) : "r"(addr));
    return d;
}

__device__ __forceinline__ void cp16(unsigned s, const void* g) {
    asm volatile("cp.async.cg.shared.global [%0], [%1], 16;" :: "r"(s), "l"(g));
}
#define CP_COMMIT()   asm volatile("cp.async.commit_group;")
#define CP_WAIT2()    asm volatile("cp.async.wait_group 2;")
#define CP_WAIT_ALL() asm volatile("cp.async.wait_all;" ::: "memory")

// ---------------- TF32 tensor-core GEMM (128x128, BK=16, 4-stage) -----------
// C[M,N] = A[M,K] @ B[K,N]; optional second output C2 = tf32(acc + bias2)
// (used to produce qw/qr in one pass). Inputs must be tf32-pre-rounded.
struct Sel4 {
    const float* A[4]; const float* B[4]; float* C[4];
    const float* bias[4]; float* C2[4]; const float* bias2[4];
};

template<bool RELU, bool CVT>
__global__ void __launch_bounds__(256)
tg(Sel4 p, int K, int lda, int ldb, int ldc,
   long offA1, long offA2, long offB1, long offB2, long offC1, long offC2,
   int nh, int bps)
{
    extern __shared__ float sm[];
    constexpr int AS = 20;
    constexpr int BSN = 136;
    constexpr int A_W = 128 * AS;       // 2560
    constexpr int B_W = 16 * BSN;       // 2176

    const int z = blockIdx.z;
    const int sel = z / bps, bz = z - sel * bps;
    const float* Ab = p.A[sel] + (long)(bz / nh) * offA1 + (long)(bz % nh) * offA2;
    const float* Bb = p.B[sel] + (long)(bz / nh) * offB1 + (long)(bz % nh) * offB2;
    float*       Cb = p.C[sel] + (long)(bz / nh) * offC1 + (long)(bz % nh) * offC2;
    const float* bias  = p.bias[sel];
    float*       Cb2   = p.C2[sel];
    const float* bias2 = p.bias2[sel];

    float* As = sm;
    float* Bs = sm + 4 * A_W;

    const int m0 = blockIdx.y * 128;
    const int n0 = blockIdx.x * 128;
    const int tid  = threadIdx.x;
    const int lane = tid & 31;
    const int wid  = tid >> 5;
    const int warp_m = wid & 1;
    const int warp_n = wid >> 1;

    float acc[4][4][4];
    #pragma unroll
    for (int i = 0; i < 4; i++)
        #pragma unroll
        for (int j = 0; j < 4; j++)
            #pragma unroll
            for (int l = 0; l < 4; l++) acc[i][j][l] = 0.f;

    const unsigned aB = (unsigned)__cvta_generic_to_shared(As);
    const unsigned bB = (unsigned)__cvta_generic_to_shared(Bs);
    const int ntile = K / 16;

    auto issue = [&](int t, int s) {
        const int k0 = t * 16;
        const unsigned ab = aB + (unsigned)(s * A_W) * 4;
        const unsigned bb = bB + (unsigned)(s * B_W) * 4;
        #pragma unroll
        for (int i = 0; i < 2; i++) {
            int e = tid + i * 256;
            int row = e >> 2, kk = (e & 3) << 2;
            cp16(ab + (unsigned)(row * AS + kk) * 4,
                 &Ab[(long)(m0 + row) * lda + k0 + kk]);
        }
        #pragma unroll
        for (int i = 0; i < 2; i++) {
            int e = tid + i * 256;
            int kk = e >> 5, n = (e & 31) << 2;
            cp16(bb + (unsigned)(kk * BSN + n) * 4,
                 &Bb[(long)(k0 + kk) * ldb + n0 + n]);
        }
    };

    auto compute = [&](int s) {
        const unsigned ab = aB + (unsigned)(s * A_W) * 4;
        const float* Bw = Bs + s * B_W;
        const int q = lane >> 3, ri = lane & 7;
        const int r = lane >> 2, c = lane & 3;
        #pragma unroll
        for (int ks = 0; ks < 2; ks++) {
            uint4 af[4];
            #pragma unroll
            for (int mt = 0; mt < 4; mt++) {
                int row = warp_m * 64 + mt * 16 + (q & 1) * 8 + ri;
                int col = ks * 8 + (q >> 1) * 4;
                af[mt] = ldsm4(ab + (unsigned)(row * AS + col) * 4);
            }
            uint2 bf[4];
            #pragma unroll
            for (int nt = 0; nt < 4; nt++) {
                int n = warp_n * 32 + nt * 8 + r;
                const float* pp = &Bw[(ks * 8 + c) * BSN + n];
                bf[nt].x = __float_as_uint(pp[0]);
                bf[nt].y = __float_as_uint(pp[4 * BSN]);
            }
            #pragma unroll
            for (int mt = 0; mt < 4; mt++)
                #pragma unroll
                for (int nt = 0; nt < 4; nt++)
                    mma_tf32(acc[mt][nt], af[mt], bf[nt]);
        }
    };

    // 4-stage pipeline, one barrier per tile
    issue(0, 0); CP_COMMIT();
    if (ntile > 1) { issue(1, 1); } CP_COMMIT();
    if (ntile > 2) { issue(2, 2); } CP_COMMIT();
    for (int t = 0; t < ntile; t++) {
        CP_WAIT2();
        __syncthreads();
        if (t + 3 < ntile) issue(t + 3, (t + 3) & 3);
        CP_COMMIT();
        compute(t & 3);
    }

    // ---- epilogue ----
    #pragma unroll
    for (int mt = 0; mt < 4; mt++) {
        int rbase = m0 + warp_m * 64 + mt * 16 + (lane >> 2);
        #pragma unroll
        for (int nt = 0; nt < 4; nt++) {
            int cbase = n0 + warp_n * 32 + nt * 8 + (lane & 3) * 2;
            float* d = acc[mt][nt];
            float b0 = 0.f, b1 = 0.f;
            if (bias) { b0 = bias[cbase]; b1 = bias[cbase + 1]; }
            float v0 = d[0] + b0, v1 = d[1] + b1;
            float v2 = d[2] + b0, v3 = d[3] + b1;
            if (RELU) {
                v0 = fmaxf(v0, 0.f); v1 = fmaxf(v1, 0.f);
                v2 = fmaxf(v2, 0.f); v3 = fmaxf(v3, 0.f);
            }
            if (CVT) {
                v0 = roundtf(v0); v1 = roundtf(v1);
                v2 = roundtf(v2); v3 = roundtf(v3);
            }
            *(float2*)&Cb[(long)rbase * ldc + cbase]       = make_float2(v0, v1);
            *(float2*)&Cb[(long)(rbase + 8) * ldc + cbase] = make_float2(v2, v3);
            if (Cb2) {
                float c0 = bias2[cbase], c1 = bias2[cbase + 1];
                *(float2*)&Cb2[(long)rbase * ldc + cbase] =
                    make_float2(roundtf(d[0] + c0), roundtf(d[1] + c1));
                *(float2*)&Cb2[(long)(rbase + 8) * ldc + cbase] =
                    make_float2(roundtf(d[2] + c0), roundtf(d[3] + c1));
            }
        }
    }
}

template<bool RELU, bool CVT>
static void launch_tg(dim3 grid, const Sel4& p, int K, int lda, int ldb, int ldc,
                      long oA1, long oA2, long oB1, long oB2, long oC1, long oC2,
                      int nh, int bps)
{
    constexpr int smem = 4 * (128 * 20 + 16 * 136) * 4;   // 75776 B
    cudaFuncSetAttribute(tg<RELU, CVT>,
                         cudaFuncAttributeMaxDynamicSharedMemorySize, smem);
    tg<RELU, CVT><<<grid, 256, smem>>>(
        p, K, lda, ldb, ldc, oA1, oA2, oB1, oB2, oC1, oC2, nh, bps);
}

// ---------------- fused flash attention with rel-shift -----------------------
// One CTA = 128 query rows of one (b,h). Online softmax, rr kept in a
// 3x64-row ring (only 64 new rows loaded per tile after the first).
// smem floats: K_s[64][68] | Vt[64][68] | rr_ring[192][68] | Pb[128][68]
#define FL_ST 68
#define FL_KS 0
#define FL_VT 4352
#define FL_RR 8704
#define FL_PB 21760
#define FL_TOT 30464

__global__ void __launch_bounds__(256, 1)
flash_kernel(const float* __restrict__ qwp, const float* __restrict__ qrp,
             const float* __restrict__ kp,  const float* __restrict__ rp,
             const float* __restrict__ vp,  float* __restrict__ avp)
{
    extern __shared__ float sm[];
    float* Vt = sm + FL_VT;
    float* Pb = sm + FL_PB;

    const int bid = blockIdx.x;
    const int it  = 7 - (bid >> 6);           // heavy blocks first
    const int bh  = bid & 63;
    const int b   = bh >> 4, h = bh & 15;
    const int i0  = it * 128;

    const int tid = threadIdx.x, lane = tid & 31, wid = tid >> 5;
    const int r0w = wid * 16;
    const int grp = lane >> 3, rw = lane & 7;
    const int r = lane >> 2, c = lane & 3;

    const long qbase  = ((long)(b * Sq + i0)) * Dm + h * 64;
    const long kvbase = ((long)b * Sq) * Dm + h * 64;

    const unsigned sK = (unsigned)__cvta_generic_to_shared(sm + FL_KS);
    const unsigned sV = (unsigned)__cvta_generic_to_shared(sm + FL_VT);
    const unsigned sR = (unsigned)__cvta_generic_to_shared(sm + FL_RR);
    const unsigned sP = (unsigned)__cvta_generic_to_shared(sm + FL_PB);

    // ---- stage Q tiles (qw -> rr area, qr -> Pb) and extract fragments ----
    uint4 qwf[8], qrf[8];
    for (int e = tid; e < 128 * 16; e += 256) {
        int row = e >> 4, c4 = (e & 15) << 2;
        cp16(sR + (unsigned)(row * FL_ST + c4) * 4, &qwp[qbase + (long)row * Dm + c4]);
        cp16(sP + (unsigned)(row * FL_ST + c4) * 4, &qrp[qbase + (long)row * Dm + c4]);
    }
    CP_COMMIT(); CP_WAIT_ALL(); __syncthreads();
    #pragma unroll
    for (int ks = 0; ks < 8; ks++) {
        unsigned off = (unsigned)((r0w + (grp & 1) * 8 + rw) * FL_ST + ks * 8 + (grp >> 1) * 4) * 4;
        qwf[ks] = ldsm4(sR + off);
        qrf[ks] = ldsm4(sP + off);
    }

    float m0v = -1e30f, m1v = -1e30f, l0v = 0.f, l1v = 0.f;
    float o_[8][4];
    #pragma unroll
    for (int i = 0; i < 8; i++)
        #pragma unroll
        for (int j = 0; j < 4; j++) o_[i][j] = 0.f;

    const int njt = (i0 >> 6) + 2;
    for (int jt = 0; jt < njt; jt++) {
        const int j0 = jt * 64;
        const int l0 = Sq - 128 + j0 - i0;    // rr window base (64-aligned, >= 0)
        __syncthreads();                       // prev-tile smem reads done

        // K tile
        for (int e = tid; e < 64 * 16; e += 256) {
            int row = e >> 4, c4 = (e & 15) << 2;
            cp16(sK + (unsigned)(row * FL_ST + c4) * 4,
                 &kp[kvbase + (long)(j0 + row) * Dm + c4]);
        }
        // rr ring: first tile loads all 192 rows; later tiles only 64 new ones
        {
            int rlo = (jt == 0) ? 0 : 128;
            for (int e = tid + rlo * 4; e < 192 * 16; e += 256) {
                int row = e >> 4, c4 = (e & 15) << 2;
                int l = l0 + row;
                int slot = (((l >> 6) % 3) << 6) + (l & 63);
                int lr = l > Sq - 1 ? Sq - 1 : l;             // clamp; masked anyway
                cp16(sR + (unsigned)(slot * FL_ST + c4) * 4,
                     &rp[kvbase + (long)lr * Dm + c4]);
            }
        }
        CP_COMMIT();
        // V tile: LDG + transposed STS -> Vt[d][j]
        {
            int jj = tid >> 2, db = (tid & 3) << 4;
            const float* vrow = &vp[kvbase + (long)(j0 + jj) * Dm + db];
            #pragma unroll
            for (int u = 0; u < 4; u++) {
                float4 t = *(const float4*)(vrow + u * 4);
                Vt[(db + u * 4 + 0) * FL_ST + jj] = t.x;
                Vt[(db + u * 4 + 1) * FL_ST + jj] = t.y;
                Vt[(db + u * 4 + 2) * FL_ST + jj] = t.z;
                Vt[(db + u * 4 + 3) * FL_ST + jj] = t.w;
            }
        }
        CP_WAIT_ALL(); __syncthreads();

        // ---- E band MMA: E[ii][d_win] -> scatter band (ii, jj=d-127+ii) ----
        {
            int dlo = 105 - r0w; if (dlo < 0) dlo = 0; dlo &= ~7;
            int dhi = (190 - r0w) & ~7;
            for (int d0 = dlo; d0 <= dhi; d0 += 16) {
                bool has2 = (d0 + 8 <= dhi);
                float e0[4] = {0.f,0.f,0.f,0.f}, e1[4] = {0.f,0.f,0.f,0.f};
                int lb = l0 + d0 + (grp >> 1) * 8;
                int slotb = (((lb >> 6) % 3) << 6) + (lb & 63);
                #pragma unroll
                for (int ks = 0; ks < 8; ks++) {
                    uint4 bf = ldsm4(sR + (unsigned)((slotb + rw) * FL_ST
                                                     + ks * 8 + (grp & 1) * 4) * 4);
                    mma_tf32(e0, qrf[ks], make_uint2(bf.x, bf.y));
                    if (has2) mma_tf32(e1, qrf[ks], make_uint2(bf.z, bf.w));
                }
                int ii0 = r0w + r, ii1 = ii0 + 8;
                int d = d0 + 2 * c;
                int ja = d - 127 + ii0, jb = d - 127 + ii1;
                if (ja     >= 0 && ja     < 64) Pb[ii0 * FL_ST + ja    ] = e0[0];
                if (ja + 1 >= 0 && ja + 1 < 64) Pb[ii0 * FL_ST + ja + 1] = e0[1];
                if (jb     >= 0 && jb     < 64) Pb[ii1 * FL_ST + jb    ] = e0[2];
                if (jb + 1 >= 0 && jb + 1 < 64) Pb[ii1 * FL_ST + jb + 1] = e0[3];
                if (has2) {
                    int ja2 = ja + 8, jb2 = jb + 8;
                    if (ja2     >= 0 && ja2     < 64) Pb[ii0 * FL_ST + ja2    ] = e1[0];
                    if (ja2 + 1 >= 0 && ja2 + 1 < 64) Pb[ii0 * FL_ST + ja2 + 1] = e1[1];
                    if (jb2     >= 0 && jb2     < 64) Pb[ii1 * FL_ST + jb2    ] = e1[2];
                    if (jb2 + 1 >= 0 && jb2 + 1 < 64) Pb[ii1 * FL_ST + jb2 + 1] = e1[3];
                }
            }
        }
        __syncwarp();

        // ---- ac MMA ----
        float s_[8][4];
        #pragma unroll
        for (int i = 0; i < 8; i++)
            #pragma unroll
            for (int j = 0; j < 4; j++) s_[i][j] = 0.f;
        #pragma unroll
        for (int ks = 0; ks < 8; ks++) {
            #pragma unroll
            for (int p = 0; p < 4; p++) {
                uint4 bf = ldsm4(sK + (unsigned)((p * 16 + (grp >> 1) * 8 + rw) * FL_ST
                                                 + ks * 8 + (grp & 1) * 4) * 4);
                mma_tf32(s_[2 * p],     qwf[ks], make_uint2(bf.x, bf.y));
                mma_tf32(s_[2 * p + 1], qwf[ks], make_uint2(bf.z, bf.w));
            }
        }

        // ---- S = (ac + E)*scale, mask, online softmax ----
        const int gi0 = i0 + r0w + r, gi1 = gi0 + 8;
        float mx0 = -1e30f, mx1 = -1e30f;
        #pragma unroll
        for (int nt = 0; nt < 8; nt++) {
            int jj = nt * 8 + 2 * c, jg = j0 + jj;
            float e00 = Pb[(r0w + r) * FL_ST + jj],     e01 = Pb[(r0w + r) * FL_ST + jj + 1];
            float e10 = Pb[(r0w + r + 8) * FL_ST + jj], e11 = Pb[(r0w + r + 8) * FL_ST + jj + 1];
            s_[nt][0] = (jg     <= gi0) ? (s_[nt][0] + e00) * 0.125f : -1e30f;
            s_[nt][1] = (jg + 1 <= gi0) ? (s_[nt][1] + e01) * 0.125f : -1e30f;
            s_[nt][2] = (jg     <= gi1) ? (s_[nt][2] + e10) * 0.125f : -1e30f;
            s_[nt][3] = (jg + 1 <= gi1) ? (s_[nt][3] + e11) * 0.125f : -1e30f;
            mx0 = fmaxf(mx0, fmaxf(s_[nt][0], s_[nt][1]));
            mx1 = fmaxf(mx1, fmaxf(s_[nt][2], s_[nt][3]));
        }
        mx0 = fmaxf(mx0, __shfl_xor_sync(0xffffffffu, mx0, 1));
        mx0 = fmaxf(mx0, __shfl_xor_sync(0xffffffffu, mx0, 2));
        mx1 = fmaxf(mx1, __shfl_xor_sync(0xffffffffu, mx1, 1));
        mx1 = fmaxf(mx1, __shfl_xor_sync(0xffffffffu, mx1, 2));
        float mn0 = fmaxf(m0v, mx0), mn1 = fmaxf(m1v, mx1);
        float a0 = __expf(m0v - mn0), a1 = __expf(m1v - mn1);
        float sum0 = 0.f, sum1 = 0.f;
        #pragma unroll
        for (int nt = 0; nt < 8; nt++) {
            int jj = nt * 8 + 2 * c;
            float p00 = __expf(s_[nt][0] - mn0), p01 = __expf(s_[nt][1] - mn0);
            float p10 = __expf(s_[nt][2] - mn1), p11 = __expf(s_[nt][3] - mn1);
            sum0 += p00 + p01; sum1 += p10 + p11;
            Pb[(r0w + r) * FL_ST + jj]         = roundtf(p00);
            Pb[(r0w + r) * FL_ST + jj + 1]     = roundtf(p01);
            Pb[(r0w + r + 8) * FL_ST + jj]     = roundtf(p10);
            Pb[(r0w + r + 8) * FL_ST + jj + 1] = roundtf(p11);
        }
        sum0 += __shfl_xor_sync(0xffffffffu, sum0, 1);
        sum0 += __shfl_xor_sync(0xffffffffu, sum0, 2);
        sum1 += __shfl_xor_sync(0xffffffffu, sum1, 1);
        sum1 += __shfl_xor_sync(0xffffffffu, sum1, 2);
        l0v = l0v * a0 + sum0; l1v = l1v * a1 + sum1;
        m0v = mn0; m1v = mn1;
        #pragma unroll
        for (int dt = 0; dt < 8; dt++) {
            o_[dt][0] *= a0; o_[dt][1] *= a0;
            o_[dt][2] *= a1; o_[dt][3] *= a1;
        }
        __syncwarp();

        // ---- PV: O += P @ V ----
        #pragma unroll
        for (int ks = 0; ks < 8; ks++) {
            uint4 af = ldsm4(sP + (unsigned)((r0w + (grp & 1) * 8 + rw) * FL_ST
                                             + ks * 8 + (grp >> 1) * 4) * 4);
            #pragma unroll
            for (int p = 0; p < 4; p++) {
                uint4 bf = ldsm4(sV + (unsigned)((p * 16 + (grp >> 1) * 8 + rw) * FL_ST
                                                 + ks * 8 + (grp & 1) * 4) * 4);
                mma_tf32(o_[2 * p],     af, make_uint2(bf.x, bf.y));
                mma_tf32(o_[2 * p + 1], af, make_uint2(bf.z, bf.w));
            }
        }
    }

    // ---- epilogue: O / l, tf32-rounded (feeds Wo GEMM) ----
    float i0v = 1.f / l0v, i1v = 1.f / l1v;
    long ob0 = ((long)(b * Sq + i0 + r0w + r)) * Dm + h * 64;
    long ob1 = ob0 + 8L * Dm;
    #pragma unroll
    for (int dt = 0; dt < 8; dt++) {
        int d = dt * 8 + 2 * c;
        *(float2*)&avp[ob0 + d] = make_float2(roundtf(o_[dt][0] * i0v), roundtf(o_[dt][1] * i0v));
        *(float2*)&avp[ob1 + d] = make_float2(roundtf(o_[dt][2] * i1v), roundtf(o_[dt][3] * i1v));
    }
}

// ---------------- input tf32 pre-round pass ---------------------------------
struct RSeg { const float4* s; float4* d; int n4; };
struct R9   { RSeg seg[9]; };

__global__ void round9_kernel(R9 r) {
    RSeg sg = r.seg[blockIdx.y];
    for (int i = blockIdx.x * blockDim.x + threadIdx.x; i < sg.n4;
         i += gridDim.x * blockDim.x) {
        float4 v = sg.s[i];
        v.x = roundtf(v.x); v.y = roundtf(v.y);
        v.z = roundtf(v.z); v.w = roundtf(v.w);
        sg.d[i] = v;
    }
}

// ---------------- reductions ----------------------------------------------
__device__ __forceinline__ float warpSum(float v) {
    #pragma unroll
    for (int o = 16; o > 0; o >>= 1) v += __shfl_xor_sync(0xffffffffu, v, o);
    return v;
}
__device__ float blockSum(float v) {
    __shared__ float red[8];
    __syncthreads();
    int lane = threadIdx.x & 31, wid = threadIdx.x >> 5;
    v = warpSum(v);
    if (lane == 0) red[wid] = v;
    __syncthreads();
    if (wid == 0) {
        float t = (lane < 8) ? red[lane] : 0.f;
        t = warpSum(t);
        if (lane == 0) red[0] = t;
    }
    __syncthreads();
    return red[0];
}

// ---------------- fused residual + LayerNorm (optional tf32 copy) -----------
__global__ void ln_kernel(const float* __restrict__ a, const float* __restrict__ b,
                          const float* __restrict__ gam, const float* __restrict__ bet,
                          float* __restrict__ out, float* __restrict__ out_tf)
{
    const long row = blockIdx.x;
    const long base = row * Dm;
    __shared__ float sbuf[Dm];
    const int tid = threadIdx.x;

    float ls = 0.f;
    for (int j = tid; j < Dm; j += blockDim.x) {
        float x = a[base + j] + b[base + j];
        sbuf[j] = x;
        ls += x;
    }
    float mu = blockSum(ls) * (1.f / Dm);

    float lv = 0.f;
    for (int j = tid; j < Dm; j += blockDim.x) {
        float d = sbuf[j] - mu;
        lv += d * d;
    }
    float var = blockSum(lv) * (1.f / Dm);
    float inv = rsqrtf(var + EPS);

    for (int j = tid; j < Dm; j += blockDim.x) {
        float y = (sbuf[j] - mu) * inv * gam[j] + bet[j];
        out[base + j] = y;
        if (out_tf) out_tf[base + j] = roundtf(y);
    }
}

// ---------------- launch ----------------------------------------------------
extern "C" void kernel_launch(void* const* d_in, const int* in_sizes, int n_in,
                              void* d_out, int out_size)
{
    const float* w      = (const float*)d_in[0];
    const float* r      = (const float*)d_in[1];
    const float* w_bias = (const float*)d_in[2];
    const float* r_bias = (const float*)d_in[3];
    const float* b1     = (const float*)d_in[12];
    const float* b2     = (const float*)d_in[14];
    const float* ln1g   = (const float*)d_in[9];
    const float* ln1b   = (const float*)d_in[10];
    const float* ln2g   = (const float*)d_in[15];
    const float* ln2b   = (const float*)d_in[16];
    float* out = (float*)d_out;

    float *k, *v, *rr, *qw, *qr, *av, *ao, *x, *xr, *h, *f;
    float *wr, *rr2, *Wqr, *Wkr, *Wvr, *Wrr, *Wor, *W1r, *W2r;
    cudaGetSymbolAddress((void**)&k,   g_k);
    cudaGetSymbolAddress((void**)&v,   g_v);
    cudaGetSymbolAddress((void**)&rr,  g_r);
    cudaGetSymbolAddress((void**)&qw,  g_qw);
    cudaGetSymbolAddress((void**)&qr,  g_qr);
    cudaGetSymbolAddress((void**)&av,  g_av);
    cudaGetSymbolAddress((void**)&ao,  g_ao);
    cudaGetSymbolAddress((void**)&x,   g_x);
    cudaGetSymbolAddress((void**)&xr,  g_xr);
    cudaGetSymbolAddress((void**)&h,   g_h);
    cudaGetSymbolAddress((void**)&f,   g_f);
    cudaGetSymbolAddress((void**)&wr,  g_wr);
    cudaGetSymbolAddress((void**)&rr2, g_rr2);
    cudaGetSymbolAddress((void**)&Wqr, g_Wqr);
    cudaGetSymbolAddress((void**)&Wkr, g_Wkr);
    cudaGetSymbolAddress((void**)&Wvr, g_Wvr);
    cudaGetSymbolAddress((void**)&Wrr, g_Wrr);
    cudaGetSymbolAddress((void**)&Wor, g_Wor);
    cudaGetSymbolAddress((void**)&W1r, g_W1r);
    cudaGetSymbolAddress((void**)&W2r, g_W2r);

    const int M = Bq * Sq;

    // 0) tf32 pre-round of raw inputs
    {
        R9 rp;
        const float* srcs[9] = { w, r, (const float*)d_in[4], (const float*)d_in[5],
                                 (const float*)d_in[6], (const float*)d_in[7],
                                 (const float*)d_in[8], (const float*)d_in[11],
                                 (const float*)d_in[13] };
        float* dsts[9] = { wr, rr2, Wqr, Wkr, Wvr, Wrr, Wor, W1r, W2r };
        int ns[9] = { Bq*Sq*Dm, Bq*Sq*Dm, Dm*Dm, Dm*Dm, Dm*Dm, Dm*Dm, Dm*Dm,
                      Dm*DIf, DIf*Dm };
        for (int i = 0; i < 9; i++) {
            rp.seg[i].s = (const float4*)srcs[i];
            rp.seg[i].d = (float4*)dsts[i];
            rp.seg[i].n4 = ns[i] / 4;
        }
        round9_kernel<<<dim3(512, 9), 256>>>(rp);
    }

    // 1) four projections in one launch; q-biases fused into Wq epilogue
    {
        Sel4 p{};
        p.A[0] = wr;  p.A[1] = wr;  p.A[2] = wr;  p.A[3] = rr2;
        p.B[0] = Wqr; p.B[1] = Wkr; p.B[2] = Wvr; p.B[3] = Wrr;
        p.C[0] = qw;  p.C[1] = k;   p.C[2] = v;   p.C[3] = rr;
        p.bias[0]  = w_bias;
        p.C2[0]    = qr;
        p.bias2[0] = r_bias;
        launch_tg<false, true>(dim3(Dm/128, M/128, 4), p,
            Dm, Dm, Dm, Dm, 0,0,0,0,0,0, 1, 1);
    }

    // 2) fused flash attention (scores + rel-shift + softmax + AV)
    cudaFuncSetAttribute(flash_kernel,
                         cudaFuncAttributeMaxDynamicSharedMemorySize, FL_TOT * 4);
    flash_kernel<<<512, 256, FL_TOT * 4>>>(qw, qr, k, rr, v, av);

    // 3) attn_out = attn_vec @ Wo
    {
        Sel4 p{};
        p.A[0] = av; p.B[0] = Wor; p.C[0] = ao;
        launch_tg<false, false>(dim3(Dm/128, M/128, 1), p,
            Dm, Dm, Dm, Dm, 0,0,0,0,0,0, 1, 1);
    }

    // 4) x = LN(w + attn_out); xr = tf32(x)
    ln_kernel<<<M, 256>>>(w, ao, ln1g, ln1b, x, xr);

    // 5) FFN
    {
        Sel4 p{};
        p.A[0] = xr; p.B[0] = W1r; p.C[0] = h; p.bias[0] = b1;
        launch_tg<true, true>(dim3(DIf/128, M/128, 1), p,
            Dm, Dm, DIf, DIf, 0,0,0,0,0,0, 1, 1);
    }
    {
        Sel4 p{};
        p.A[0] = h; p.B[0] = W2r; p.C[0] = f; p.bias[0] = b2;
        launch_tg<false, false>(dim3(Dm/128, M/128, 1), p,
            DIf, DIf, Dm, Dm, 0,0,0,0,0,0, 1, 1);
    }

    // 6) out = LN(x + f)
    ln_kernel<<<M, 256>>>(x, f, ln2g, ln2b, out, nullptr);
}

// round 10
// speedup vs baseline: 1.3895x; 1.3895x over previous
#include <cuda_runtime.h>
#include <cuda_fp16.h>
#include <math.h>
#include <cstdint>

// Problem constants
#define Bq  4
#define Sq  1024
#define Dm  1024
#define NHh 16
#define DHh 64
#define DIf 4096
#define EPS 1e-5f

// ---------------- scratch (static device globals; no allocations) ----------
__device__ float  g_k [Bq*Sq*Dm];
__device__ float  g_v [Bq*Sq*Dm];
__device__ float  g_r [Bq*Sq*Dm];
__device__ float  g_qw[Bq*Sq*Dm];
__device__ float  g_qr[Bq*Sq*Dm];
__device__ float  g_ao[Bq*Sq*Dm];
__device__ float  g_x [Bq*Sq*Dm];
__device__ float  g_f [Bq*Sq*Dm];
// fp16 operands
__device__ __half g_avh[Bq*Sq*Dm];
__device__ __half g_xh [Bq*Sq*Dm];
__device__ __half g_hh [Bq*Sq*DIf];
__device__ __half g_wh [Bq*Sq*Dm];
__device__ __half g_rh [Bq*Sq*Dm];
// weights TRANSPOSED ([N][K] row-major), fp16
__device__ __half g_Wqt[Dm*Dm];
__device__ __half g_Wkt[Dm*Dm];
__device__ __half g_Wvt[Dm*Dm];
__device__ __half g_Wrt[Dm*Dm];
__device__ __half g_Wot[Dm*Dm];
__device__ __half g_W1t[Dm*DIf];
__device__ __half g_W2t[DIf*Dm];

// ---------------- helpers ----------------------------------------------------
__device__ __forceinline__ unsigned f2tf(float v) {
    unsigned r;
    asm("cvt.rna.tf32.f32 %0, %1;" : "=r"(r) : "f"(v));
    return r;
}
__device__ __forceinline__ float roundtf(float v) { return __uint_as_float(f2tf(v)); }

__device__ __forceinline__ void mma_tf32(float* d, const uint4& a, const uint2& b) {
    asm volatile(
        "mma.sync.aligned.m16n8k8.row.col.f32.tf32.tf32.f32 "
        "{%0,%1,%2,%3}, {%4,%5,%6,%7}, {%8,%9}, {%0,%1,%2,%3};"
        : "+f"(d[0]), "+f"(d[1]), "+f"(d[2]), "+f"(d[3])
        : "r"(a.x), "r"(a.y), "r"(a.z), "r"(a.w), "r"(b.x), "r"(b.y));
}

__device__ __forceinline__ void mma_f16(float* d, const uint4& a,
                                        uint32_t b0, uint32_t b1) {
    asm volatile(
        "mma.sync.aligned.m16n8k16.row.col.f32.f16.f16.f32 "
        "{%0,%1,%2,%3}, {%4,%5,%6,%7}, {%8,%9}, {%0,%1,%2,%3};"
        : "+f"(d[0]), "+f"(d[1]), "+f"(d[2]), "+f"(d[3])
        : "r"(a.x), "r"(a.y), "r"(a.z), "r"(a.w), "r"(b0), "r"(b1));
}

__device__ __forceinline__ uint4 ldsm4(unsigned addr) {
    uint4 d;
    asm volatile("ldmatrix.sync.aligned.m8n8.x4.shared.b16 {%0,%1,%2,%3}, [%4];"
                 : "=r"(d.x), "=r"(d.y), "=r"(d.z), "=r"(d.w) : "r"(addr));
    return d;
}

__device__ __forceinline__ void cp16(unsigned s, const void* g) {
    asm volatile("cp.async.cg.shared.global [%0], [%1], 16;" :: "r"(s), "l"(g));
}
#define CP_COMMIT()   asm volatile("cp.async.commit_group;")
#define CP_WAIT2()    asm volatile("cp.async.wait_group 2;")
#define CP_WAIT_ALL() asm volatile("cp.async.wait_all;" ::: "memory")

// ---------------- FP16 tensor-core GEMM (128x128, BK=32, 4-stage) -----------
// C[M,N] = A[M,K] @ Bt[N,K]^T, both fp16 row-major (K-major).
// OUT: 0 = fp32 C, 1 = fp32 tf32-rounded C (+ optional dual C2), 2 = fp16 Ch.
struct SelH {
    const __half* A[4]; const __half* B[4];
    float* C[4]; const float* bias[4];
    float* C2[4]; const float* bias2[4];
    __half* Ch[4];
};

#define HG_TILE  (128 * 80)          // bytes per operand per stage
#define HG_STG   (2 * HG_TILE)       // 20480
#define HG_SMEM  (4 * HG_STG)        // 81920

template<bool RELU, int OUT>
__global__ void __launch_bounds__(256)
hg(SelH p, int K, int ldc)
{
    extern __shared__ __align__(16) char smraw[];
    const uint32_t sb = (uint32_t)__cvta_generic_to_shared(smraw);

    const int z   = blockIdx.z;
    const int tid = threadIdx.x, lane = tid & 31, wid = tid >> 5;
    const int warp_m = wid & 1, warp_n = wid >> 1;
    const long m0 = (long)blockIdx.y * 128, n0 = (long)blockIdx.x * 128;

    const __half* A  = p.A[z] + m0 * K;
    const __half* Bt = p.B[z] + n0 * K;
    const float* bias  = p.bias[z]  ? p.bias[z]  + n0 : nullptr;
    float*       C     = p.C[z]     ? p.C[z]     + m0 * ldc + n0 : nullptr;
    float*       C2    = p.C2[z]    ? p.C2[z]    + m0 * ldc + n0 : nullptr;
    const float* bias2 = p.bias2[z] ? p.bias2[z] + n0 : nullptr;
    __half*      Ch    = p.Ch[z]    ? p.Ch[z]    + m0 * ldc + n0 : nullptr;

    float acc[4][4][4];
    #pragma unroll
    for (int i = 0; i < 4; i++)
        #pragma unroll
        for (int j = 0; j < 4; j++)
            #pragma unroll
            for (int l = 0; l < 4; l++) acc[i][j][l] = 0.f;

    const int ntile = K >> 5;

    auto issue = [&](int c) {
        const int st = c & 3;
        const int k0 = c << 5;
        const uint32_t ab = sb + (uint32_t)st * HG_STG;
        const uint32_t bb = ab + HG_TILE;
        #pragma unroll
        for (int i = 0; i < 2; i++) {
            int e = tid + i * 256;
            int row = e >> 2, sg = e & 3;
            cp16(ab + (uint32_t)(row * 80 + sg * 16),
                 &A[(long)row * K + k0 + sg * 8]);
        }
        #pragma unroll
        for (int i = 0; i < 2; i++) {
            int e = tid + i * 256;
            int row = e >> 2, sg = e & 3;
            cp16(bb + (uint32_t)(row * 80 + sg * 16),
                 &Bt[(long)row * K + k0 + sg * 8]);
        }
    };

    auto compute = [&](int st) {
        const uint32_t ab = sb + (uint32_t)st * HG_STG;
        const uint32_t bb = ab + HG_TILE;
        const int rw = lane & 7, grp = lane >> 3;
        const uint32_t acol = (uint32_t)((grp >> 1) * 16);
        const uint32_t rsel = (uint32_t)((grp & 1) * 8 + rw);
        #pragma unroll
        for (int kb = 0; kb < 2; kb++) {
            uint4 af[4];
            #pragma unroll
            for (int mt = 0; mt < 4; mt++)
                af[mt] = ldsm4(ab + (uint32_t)(warp_m * 64 + mt * 16 + rsel) * 80
                               + kb * 32 + acol);
            uint4 bq[2];
            #pragma unroll
            for (int nb = 0; nb < 2; nb++)
                bq[nb] = ldsm4(bb + (uint32_t)(warp_n * 32 + nb * 16 + rsel) * 80
                               + kb * 32 + acol);
            #pragma unroll
            for (int mt = 0; mt < 4; mt++)
                #pragma unroll
                for (int nt = 0; nt < 4; nt++) {
                    uint32_t b0 = (nt & 1) ? bq[nt >> 1].y : bq[nt >> 1].x;
                    uint32_t b1 = (nt & 1) ? bq[nt >> 1].w : bq[nt >> 1].z;
                    mma_f16(acc[mt][nt], af[mt], b0, b1);
                }
        }
    };

    // 4-stage pipeline; empty commits keep wait_group accounting exact
    issue(0); CP_COMMIT();
    if (ntile > 1) issue(1);
    CP_COMMIT();
    if (ntile > 2) issue(2);
    CP_COMMIT();
    for (int t = 0; t < ntile; t++) {
        CP_WAIT2();
        __syncthreads();
        if (t + 3 < ntile) issue(t + 3);
        CP_COMMIT();
        compute(t & 3);
    }

    // ---- epilogue ----
    #pragma unroll
    for (int mt = 0; mt < 4; mt++) {
        int rbase = warp_m * 64 + mt * 16 + (lane >> 2);
        #pragma unroll
        for (int nt = 0; nt < 4; nt++) {
            int cbase = warp_n * 32 + nt * 8 + (lane & 3) * 2;
            float* d = acc[mt][nt];
            float b0 = 0.f, b1 = 0.f;
            if (bias) { b0 = bias[cbase]; b1 = bias[cbase + 1]; }
            float v0 = d[0] + b0, v1 = d[1] + b1;
            float v2 = d[2] + b0, v3 = d[3] + b1;
            if (RELU) {
                v0 = fmaxf(v0, 0.f); v1 = fmaxf(v1, 0.f);
                v2 = fmaxf(v2, 0.f); v3 = fmaxf(v3, 0.f);
            }
            if (OUT == 2) {
                *(__half2*)&Ch[(long)rbase * ldc + cbase]       = __floats2half2_rn(v0, v1);
                *(__half2*)&Ch[(long)(rbase + 8) * ldc + cbase] = __floats2half2_rn(v2, v3);
            } else {
                if (OUT == 1) {
                    v0 = roundtf(v0); v1 = roundtf(v1);
                    v2 = roundtf(v2); v3 = roundtf(v3);
                }
                *(float2*)&C[(long)rbase * ldc + cbase]       = make_float2(v0, v1);
                *(float2*)&C[(long)(rbase + 8) * ldc + cbase] = make_float2(v2, v3);
                if (C2) {
                    float c0 = bias2[cbase], c1 = bias2[cbase + 1];
                    *(float2*)&C2[(long)rbase * ldc + cbase] =
                        make_float2(roundtf(d[0] + c0), roundtf(d[1] + c1));
                    *(float2*)&C2[(long)(rbase + 8) * ldc + cbase] =
                        make_float2(roundtf(d[2] + c0), roundtf(d[3] + c1));
                }
            }
        }
    }
}

template<bool RELU, int OUT>
static void launch_hg(dim3 grid, const SelH& p, int K, int ldc)
{
    cudaFuncSetAttribute(hg<RELU, OUT>,
                         cudaFuncAttributeMaxDynamicSharedMemorySize, HG_SMEM);
    hg<RELU, OUT><<<grid, 256, HG_SMEM>>>(p, K, ldc);
}

// ---------------- input conversion passes ------------------------------------
__global__ void roundh_kernel(const float4* __restrict__ s0, __half* __restrict__ d0,
                              const float4* __restrict__ s1, __half* __restrict__ d1,
                              int n4) {
    const float4* s = blockIdx.y ? s1 : s0;
    __half*       d = blockIdx.y ? d1 : d0;
    for (int i = blockIdx.x * blockDim.x + threadIdx.x; i < n4;
         i += gridDim.x * blockDim.x) {
        float4 v = s[i];
        *(__half2*)&d[4 * i]     = __floats2half2_rn(v.x, v.y);
        *(__half2*)&d[4 * i + 2] = __floats2half2_rn(v.z, v.w);
    }
}

struct T7 { const float* in[7]; __half* out[7]; int K[7]; int N[7]; };

__global__ void txp_kernel(T7 t) {
    __shared__ float tb[32][33];
    const int z = blockIdx.z;
    const int K_ = t.K[z], N_ = t.N[z];
    const int n0 = blockIdx.x * 32, k0 = blockIdx.y * 32;
    if (n0 >= N_ || k0 >= K_) return;
    const int tx = threadIdx.x & 31, ty = threadIdx.x >> 5;
    #pragma unroll
    for (int i = 0; i < 32; i += 8)
        tb[ty + i][tx] = t.in[z][(long)(k0 + ty + i) * N_ + n0 + tx];
    __syncthreads();
    #pragma unroll
    for (int i = 0; i < 32; i += 8)
        t.out[z][(long)(n0 + ty + i) * K_ + k0 + tx] = __float2half_rn(tb[tx][ty + i]);
}

// ---------------- fused flash attention with rel-shift (tf32, fp16 out) ------
#define FL_ST 68
#define FL_KS 0
#define FL_VT 4352
#define FL_RR 8704
#define FL_PB 21760
#define FL_TOT 30464

__global__ void __launch_bounds__(256, 1)
flash_kernel(const float* __restrict__ qwp, const float* __restrict__ qrp,
             const float* __restrict__ kp,  const float* __restrict__ rp,
             const float* __restrict__ vp,  __half* __restrict__ avph)
{
    extern __shared__ float sm[];
    float* Vt = sm + FL_VT;
    float* Pb = sm + FL_PB;

    const int bid = blockIdx.x;
    const int it  = 7 - (bid >> 6);
    const int bh  = bid & 63;
    const int b   = bh >> 4, h = bh & 15;
    const int i0  = it * 128;

    const int tid = threadIdx.x, lane = tid & 31, wid = tid >> 5;
    const int r0w = wid * 16;
    const int grp = lane >> 3, rw = lane & 7;
    const int r = lane >> 2, c = lane & 3;

    const long qbase  = ((long)(b * Sq + i0)) * Dm + h * 64;
    const long kvbase = ((long)b * Sq) * Dm + h * 64;

    const unsigned sK = (unsigned)__cvta_generic_to_shared(sm + FL_KS);
    const unsigned sV = (unsigned)__cvta_generic_to_shared(sm + FL_VT);
    const unsigned sR = (unsigned)__cvta_generic_to_shared(sm + FL_RR);
    const unsigned sP = (unsigned)__cvta_generic_to_shared(sm + FL_PB);

    uint4 qwf[8], qrf[8];
    for (int e = tid; e < 128 * 16; e += 256) {
        int row = e >> 4, c4 = (e & 15) << 2;
        cp16(sR + (unsigned)(row * FL_ST + c4) * 4, &qwp[qbase + (long)row * Dm + c4]);
        cp16(sP + (unsigned)(row * FL_ST + c4) * 4, &qrp[qbase + (long)row * Dm + c4]);
    }
    CP_COMMIT(); CP_WAIT_ALL(); __syncthreads();
    #pragma unroll
    for (int ks = 0; ks < 8; ks++) {
        unsigned off = (unsigned)((r0w + (grp & 1) * 8 + rw) * FL_ST + ks * 8 + (grp >> 1) * 4) * 4;
        qwf[ks] = ldsm4(sR + off);
        qrf[ks] = ldsm4(sP + off);
    }

    float m0v = -1e30f, m1v = -1e30f, l0v = 0.f, l1v = 0.f;
    float o_[8][4];
    #pragma unroll
    for (int i = 0; i < 8; i++)
        #pragma unroll
        for (int j = 0; j < 4; j++) o_[i][j] = 0.f;

    const int njt = (i0 >> 6) + 2;
    for (int jt = 0; jt < njt; jt++) {
        const int j0 = jt * 64;
        const int l0 = Sq - 128 + j0 - i0;
        __syncthreads();

        for (int e = tid; e < 64 * 16; e += 256) {
            int row = e >> 4, c4 = (e & 15) << 2;
            cp16(sK + (unsigned)(row * FL_ST + c4) * 4,
                 &kp[kvbase + (long)(j0 + row) * Dm + c4]);
        }
        {
            int rlo = (jt == 0) ? 0 : 128;
            for (int e = tid + rlo * 4; e < 192 * 16; e += 256) {
                int row = e >> 4, c4 = (e & 15) << 2;
                int l = l0 + row;
                int slot = (((l >> 6) % 3) << 6) + (l & 63);
                int lr = l > Sq - 1 ? Sq - 1 : l;
                cp16(sR + (unsigned)(slot * FL_ST + c4) * 4,
                     &rp[kvbase + (long)lr * Dm + c4]);
            }
        }
        CP_COMMIT();
        {
            int jj = tid >> 2, db = (tid & 3) << 4;
            const float* vrow = &vp[kvbase + (long)(j0 + jj) * Dm + db];
            #pragma unroll
            for (int u = 0; u < 4; u++) {
                float4 t = *(const float4*)(vrow + u * 4);
                Vt[(db + u * 4 + 0) * FL_ST + jj] = t.x;
                Vt[(db + u * 4 + 1) * FL_ST + jj] = t.y;
                Vt[(db + u * 4 + 2) * FL_ST + jj] = t.z;
                Vt[(db + u * 4 + 3) * FL_ST + jj] = t.w;
            }
        }
        CP_WAIT_ALL(); __syncthreads();

        {
            int dlo = 105 - r0w; if (dlo < 0) dlo = 0; dlo &= ~7;
            int dhi = (190 - r0w) & ~7;
            for (int d0 = dlo; d0 <= dhi; d0 += 16) {
                bool has2 = (d0 + 8 <= dhi);
                float e0[4] = {0.f,0.f,0.f,0.f}, e1[4] = {0.f,0.f,0.f,0.f};
                int lb = l0 + d0 + (grp >> 1) * 8;
                int slotb = (((lb >> 6) % 3) << 6) + (lb & 63);
                #pragma unroll
                for (int ks = 0; ks < 8; ks++) {
                    uint4 bf = ldsm4(sR + (unsigned)((slotb + rw) * FL_ST
                                                     + ks * 8 + (grp & 1) * 4) * 4);
                    mma_tf32(e0, qrf[ks], make_uint2(bf.x, bf.y));
                    if (has2) mma_tf32(e1, qrf[ks], make_uint2(bf.z, bf.w));
                }
                int ii0 = r0w + r, ii1 = ii0 + 8;
                int d = d0 + 2 * c;
                int ja = d - 127 + ii0, jb = d - 127 + ii1;
                if (ja     >= 0 && ja     < 64) Pb[ii0 * FL_ST + ja    ] = e0[0];
                if (ja + 1 >= 0 && ja + 1 < 64) Pb[ii0 * FL_ST + ja + 1] = e0[1];
                if (jb     >= 0 && jb     < 64) Pb[ii1 * FL_ST + jb    ] = e0[2];
                if (jb + 1 >= 0 && jb + 1 < 64) Pb[ii1 * FL_ST + jb + 1] = e0[3];
                if (has2) {
                    int ja2 = ja + 8, jb2 = jb + 8;
                    if (ja2     >= 0 && ja2     < 64) Pb[ii0 * FL_ST + ja2    ] = e1[0];
                    if (ja2 + 1 >= 0 && ja2 + 1 < 64) Pb[ii0 * FL_ST + ja2 + 1] = e1[1];
                    if (jb2     >= 0 && jb2     < 64) Pb[ii1 * FL_ST + jb2    ] = e1[2];
                    if (jb2 + 1 >= 0 && jb2 + 1 < 64) Pb[ii1 * FL_ST + jb2 + 1] = e1[3];
                }
            }
        }
        __syncwarp();

        float s_[8][4];
        #pragma unroll
        for (int i = 0; i < 8; i++)
            #pragma unroll
            for (int j = 0; j < 4; j++) s_[i][j] = 0.f;
        #pragma unroll
        for (int ks = 0; ks < 8; ks++) {
            #pragma unroll
            for (int p = 0; p < 4; p++) {
                uint4 bf = ldsm4(sK + (unsigned)((p * 16 + (grp >> 1) * 8 + rw) * FL_ST
                                                 + ks * 8 + (grp & 1) * 4) * 4);
                mma_tf32(s_[2 * p],     qwf[ks], make_uint2(bf.x, bf.y));
                mma_tf32(s_[2 * p + 1], qwf[ks], make_uint2(bf.z, bf.w));
            }
        }

        const int gi0 = i0 + r0w + r, gi1 = gi0 + 8;
        float mx0 = -1e30f, mx1 = -1e30f;
        #pragma unroll
        for (int nt = 0; nt < 8; nt++) {
            int jj = nt * 8 + 2 * c, jg = j0 + jj;
            float e00 = Pb[(r0w + r) * FL_ST + jj],     e01 = Pb[(r0w + r) * FL_ST + jj + 1];
            float e10 = Pb[(r0w + r + 8) * FL_ST + jj], e11 = Pb[(r0w + r + 8) * FL_ST + jj + 1];
            s_[nt][0] = (jg     <= gi0) ? (s_[nt][0] + e00) * 0.125f : -1e30f;
            s_[nt][1] = (jg + 1 <= gi0) ? (s_[nt][1] + e01) * 0.125f : -1e30f;
            s_[nt][2] = (jg     <= gi1) ? (s_[nt][2] + e10) * 0.125f : -1e30f;
            s_[nt][3] = (jg + 1 <= gi1) ? (s_[nt][3] + e11) * 0.125f : -1e30f;
            mx0 = fmaxf(mx0, fmaxf(s_[nt][0], s_[nt][1]));
            mx1 = fmaxf(mx1, fmaxf(s_[nt][2], s_[nt][3]));
        }
        mx0 = fmaxf(mx0, __shfl_xor_sync(0xffffffffu, mx0, 1));
        mx0 = fmaxf(mx0, __shfl_xor_sync(0xffffffffu, mx0, 2));
        mx1 = fmaxf(mx1, __shfl_xor_sync(0xffffffffu, mx1, 1));
        mx1 = fmaxf(mx1, __shfl_xor_sync(0xffffffffu, mx1, 2));
        float mn0 = fmaxf(m0v, mx0), mn1 = fmaxf(m1v, mx1);
        float a0 = __expf(m0v - mn0), a1 = __expf(m1v - mn1);
        float sum0 = 0.f, sum1 = 0.f;
        #pragma unroll
        for (int nt = 0; nt < 8; nt++) {
            int jj = nt * 8 + 2 * c;
            float p00 = __expf(s_[nt][0] - mn0), p01 = __expf(s_[nt][1] - mn0);
            float p10 = __expf(s_[nt][2] - mn1), p11 = __expf(s_[nt][3] - mn1);
            sum0 += p00 + p01; sum1 += p10 + p11;
            Pb[(r0w + r) * FL_ST + jj]         = roundtf(p00);
            Pb[(r0w + r) * FL_ST + jj + 1]     = roundtf(p01);
            Pb[(r0w + r + 8) * FL_ST + jj]     = roundtf(p10);
            Pb[(r0w + r + 8) * FL_ST + jj + 1] = roundtf(p11);
        }
        sum0 += __shfl_xor_sync(0xffffffffu, sum0, 1);
        sum0 += __shfl_xor_sync(0xffffffffu, sum0, 2);
        sum1 += __shfl_xor_sync(0xffffffffu, sum1, 1);
        sum1 += __shfl_xor_sync(0xffffffffu, sum1, 2);
        l0v = l0v * a0 + sum0; l1v = l1v * a1 + sum1;
        m0v = mn0; m1v = mn1;
        #pragma unroll
        for (int dt = 0; dt < 8; dt++) {
            o_[dt][0] *= a0; o_[dt][1] *= a0;
            o_[dt][2] *= a1; o_[dt][3] *= a1;
        }
        __syncwarp();

        #pragma unroll
        for (int ks = 0; ks < 8; ks++) {
            uint4 af = ldsm4(sP + (unsigned)((r0w + (grp & 1) * 8 + rw) * FL_ST
                                             + ks * 8 + (grp >> 1) * 4) * 4);
            #pragma unroll
            for (int p = 0; p < 4; p++) {
                uint4 bf = ldsm4(sV + (unsigned)((p * 16 + (grp >> 1) * 8 + rw) * FL_ST
                                                 + ks * 8 + (grp & 1) * 4) * 4);
                mma_tf32(o_[2 * p],     af, make_uint2(bf.x, bf.y));
                mma_tf32(o_[2 * p + 1], af, make_uint2(bf.z, bf.w));
            }
        }
    }

    // ---- epilogue: O / l, fp16 (feeds Wo hgemm) ----
    float i0v = 1.f / l0v, i1v = 1.f / l1v;
    long ob0 = ((long)(b * Sq + i0 + r0w + r)) * Dm + h * 64;
    long ob1 = ob0 + 8L * Dm;
    #pragma unroll
    for (int dt = 0; dt < 8; dt++) {
        int d = dt * 8 + 2 * c;
        *(__half2*)&avph[ob0 + d] = __floats2half2_rn(o_[dt][0] * i0v, o_[dt][1] * i0v);
        *(__half2*)&avph[ob1 + d] = __floats2half2_rn(o_[dt][2] * i1v, o_[dt][3] * i1v);
    }
}

// ---------------- reductions / LN --------------------------------------------
__device__ __forceinline__ float warpSum(float v) {
    #pragma unroll
    for (int o = 16; o > 0; o >>= 1) v += __shfl_xor_sync(0xffffffffu, v, o);
    return v;
}
__device__ float blockSum(float v) {
    __shared__ float red[8];
    __syncthreads();
    int lane = threadIdx.x & 31, wid = threadIdx.x >> 5;
    v = warpSum(v);
    if (lane == 0) red[wid] = v;
    __syncthreads();
    if (wid == 0) {
        float t = (lane < 8) ? red[lane] : 0.f;
        t = warpSum(t);
        if (lane == 0) red[0] = t;
    }
    __syncthreads();
    return red[0];
}

__global__ void ln_kernel(const float* __restrict__ a, const float* __restrict__ b,
                          const float* __restrict__ gam, const float* __restrict__ bet,
                          float* __restrict__ out, __half* __restrict__ out_h)
{
    const long row = blockIdx.x;
    const long base = row * Dm;
    __shared__ float sbuf[Dm];
    const int tid = threadIdx.x;

    float ls = 0.f;
    for (int j = tid; j < Dm; j += blockDim.x) {
        float x = a[base + j] + b[base + j];
        sbuf[j] = x;
        ls += x;
    }
    float mu = blockSum(ls) * (1.f / Dm);

    float lv = 0.f;
    for (int j = tid; j < Dm; j += blockDim.x) {
        float d = sbuf[j] - mu;
        lv += d * d;
    }
    float var = blockSum(lv) * (1.f / Dm);
    float inv = rsqrtf(var + EPS);

    for (int j = tid; j < Dm; j += blockDim.x) {
        float y = (sbuf[j] - mu) * inv * gam[j] + bet[j];
        out[base + j] = y;
        if (out_h) out_h[base + j] = __float2half_rn(y);
    }
}

// ---------------- launch ----------------------------------------------------
extern "C" void kernel_launch(void* const* d_in, const int* in_sizes, int n_in,
                              void* d_out, int out_size)
{
    const float* w      = (const float*)d_in[0];
    const float* r      = (const float*)d_in[1];
    const float* w_bias = (const float*)d_in[2];
    const float* r_bias = (const float*)d_in[3];
    const float* b1     = (const float*)d_in[12];
    const float* b2     = (const float*)d_in[14];
    const float* ln1g   = (const float*)d_in[9];
    const float* ln1b   = (const float*)d_in[10];
    const float* ln2g   = (const float*)d_in[15];
    const float* ln2b   = (const float*)d_in[16];
    float* out = (float*)d_out;

    float *k, *v, *rr, *qw, *qr, *ao, *x, *f;
    __half *avh, *xh, *hh, *wh, *rh, *Wqt, *Wkt, *Wvt, *Wrt, *Wot, *W1t, *W2t;
    cudaGetSymbolAddress((void**)&k,   g_k);
    cudaGetSymbolAddress((void**)&v,   g_v);
    cudaGetSymbolAddress((void**)&rr,  g_r);
    cudaGetSymbolAddress((void**)&qw,  g_qw);
    cudaGetSymbolAddress((void**)&qr,  g_qr);
    cudaGetSymbolAddress((void**)&ao,  g_ao);
    cudaGetSymbolAddress((void**)&x,   g_x);
    cudaGetSymbolAddress((void**)&f,   g_f);
    cudaGetSymbolAddress((void**)&avh, g_avh);
    cudaGetSymbolAddress((void**)&xh,  g_xh);
    cudaGetSymbolAddress((void**)&hh,  g_hh);
    cudaGetSymbolAddress((void**)&wh,  g_wh);
    cudaGetSymbolAddress((void**)&rh,  g_rh);
    cudaGetSymbolAddress((void**)&Wqt, g_Wqt);
    cudaGetSymbolAddress((void**)&Wkt, g_Wkt);
    cudaGetSymbolAddress((void**)&Wvt, g_Wvt);
    cudaGetSymbolAddress((void**)&Wrt, g_Wrt);
    cudaGetSymbolAddress((void**)&Wot, g_Wot);
    cudaGetSymbolAddress((void**)&W1t, g_W1t);
    cudaGetSymbolAddress((void**)&W2t, g_W2t);

    const int M = Bq * Sq;

    // 0a) fp16 conversion of activations w, r
    roundh_kernel<<<dim3(512, 2), 256>>>((const float4*)w, wh,
                                         (const float4*)r, rh,
                                         Bq * Sq * Dm / 4);

    // 0b) transpose + fp16 of the 7 weights (Wt[n][k] = W[k][n])
    {
        T7 t{};
        const float* ins[7] = { (const float*)d_in[4], (const float*)d_in[5],
                                (const float*)d_in[6], (const float*)d_in[7],
                                (const float*)d_in[8], (const float*)d_in[11],
                                (const float*)d_in[13] };
        __half* outs[7] = { Wqt, Wkt, Wvt, Wrt, Wot, W1t, W2t };
        int Ks[7] = { Dm, Dm, Dm, Dm, Dm, Dm, DIf };
        int Ns[7] = { Dm, Dm, Dm, Dm, Dm, DIf, Dm };
        for (int i = 0; i < 7; i++) { t.in[i]=ins[i]; t.out[i]=outs[i]; t.K[i]=Ks[i]; t.N[i]=Ns[i]; }
        txp_kernel<<<dim3(128, 128, 7), 256>>>(t);
    }

    // 1) four projections (fp16 MMA); q-biases fused (qw & qr dual output);
    //    outputs fp32 tf32-rounded for the flash kernel
    {
        SelH p{};
        p.A[0] = wh;  p.A[1] = wh;  p.A[2] = wh;  p.A[3] = rh;
        p.B[0] = Wqt; p.B[1] = Wkt; p.B[2] = Wvt; p.B[3] = Wrt;
        p.C[0] = qw;  p.C[1] = k;   p.C[2] = v;   p.C[3] = rr;
        p.bias[0]  = w_bias;
        p.C2[0]    = qr;
        p.bias2[0] = r_bias;
        launch_hg<false, 1>(dim3(Dm / 128, M / 128, 4), p, Dm, Dm);
    }

    // 2) fused flash attention (tf32 scores + rel-shift + softmax + AV; fp16 out)
    cudaFuncSetAttribute(flash_kernel,
                         cudaFuncAttributeMaxDynamicSharedMemorySize, FL_TOT * 4);
    flash_kernel<<<512, 256, FL_TOT * 4>>>(qw, qr, k, rr, v, avh);

    // 3) attn_out = av @ Wo (fp16 MMA, fp32 out)
    {
        SelH p{};
        p.A[0] = avh; p.B[0] = Wot; p.C[0] = ao;
        launch_hg<false, 0>(dim3(Dm / 128, M / 128, 1), p, Dm, Dm);
    }

    // 4) x = LN(w + attn_out); xh = fp16(x)
    ln_kernel<<<M, 256>>>(w, ao, ln1g, ln1b, x, xh);

    // 5) FFN: hh = fp16(relu(x @ W1 + b1)); f = hh @ W2 + b2
    {
        SelH p{};
        p.A[0] = xh; p.B[0] = W1t; p.bias[0] = b1; p.Ch[0] = hh;
        launch_hg<true, 2>(dim3(DIf / 128, M / 128, 1), p, Dm, DIf);
    }
    {
        SelH p{};
        p.A[0] = hh; p.B[0] = W2t; p.bias[0] = b2; p.C[0] = f;
        launch_hg<false, 0>(dim3(Dm / 128, M / 128, 1), p, DIf, Dm);
    }

    // 6) out = LN(x + f)
    ln_kernel<<<M, 256>>>(x, f, ln2g, ln2b, out, nullptr);
}

// round 12
// speedup vs baseline: 1.5660x; 1.1271x over previous
#include <cuda_runtime.h>
#include <cuda_fp16.h>
#include <math.h>
#include <cstdint>

// Problem constants
#define Bq  4
#define Sq  1024
#define Dm  1024
#define NHh 16
#define DHh 64
#define DIf 4096
#define EPS 1e-5f

// ---------------- scratch (static device globals; no allocations) ----------
__device__ float  g_ao[Bq*Sq*Dm];
__device__ float  g_x [Bq*Sq*Dm];
__device__ float  g_f [Bq*Sq*Dm];
// fp16 operands
__device__ __half g_qwh[Bq*Sq*Dm];
__device__ __half g_qrh[Bq*Sq*Dm];
__device__ __half g_kh [Bq*Sq*Dm];
__device__ __half g_vh [Bq*Sq*Dm];
__device__ __half g_rrh[Bq*Sq*Dm];
__device__ __half g_avh[Bq*Sq*Dm];
__device__ __half g_xh [Bq*Sq*Dm];
__device__ __half g_hh [Bq*Sq*DIf];
__device__ __half g_wh [Bq*Sq*Dm];
__device__ __half g_rh [Bq*Sq*Dm];
// weights TRANSPOSED ([N][K] row-major), fp16
__device__ __half g_Wqt[Dm*Dm];
__device__ __half g_Wkt[Dm*Dm];
__device__ __half g_Wvt[Dm*Dm];
__device__ __half g_Wrt[Dm*Dm];
__device__ __half g_Wot[Dm*Dm];
__device__ __half g_W1t[Dm*DIf];
__device__ __half g_W2t[DIf*Dm];

// ---------------- helpers ----------------------------------------------------
__device__ __forceinline__ void mma_f16(float* d, const uint4& a,
                                        uint32_t b0, uint32_t b1) {
    asm volatile(
        "mma.sync.aligned.m16n8k16.row.col.f32.f16.f16.f32 "
        "{%0,%1,%2,%3}, {%4,%5,%6,%7}, {%8,%9}, {%0,%1,%2,%3};"
        : "+f"(d[0]), "+f"(d[1]), "+f"(d[2]), "+f"(d[3])
        : "r"(a.x), "r"(a.y), "r"(a.z), "r"(a.w), "r"(b0), "r"(b1));
}

__device__ __forceinline__ uint4 ldsm4(unsigned addr) {
    uint4 d;
    asm volatile("ldmatrix.sync.aligned.m8n8.x4.shared.b16 {%0,%1,%2,%3}, [%4];"
                 : "=r"(d.x), "=r"(d.y), "=r"(d.z), "=r"(d.w) : "r"(addr));
    return d;
}

__device__ __forceinline__ void cp16(unsigned s, const void* g) {
    asm volatile("cp.async.cg.shared.global [%0], [%1], 16;" :: "r"(s), "l"(g));
}
#define CP_COMMIT()   asm volatile("cp.async.commit_group;")
#define CP_WAIT2()    asm volatile("cp.async.wait_group 2;")
#define CP_WAIT_ALL() asm volatile("cp.async.wait_all;" ::: "memory")

// ---------------- FP16 tensor-core GEMM (128x128, BK=32, 4-stage) -----------
// C[M,N] = A[M,K] @ Bt[N,K]^T, both fp16 row-major (K-major).
// OUT: 0 = fp32 C, 2 = fp16 Ch (+optional dual Ch2 with bias2).
struct SelH {
    const __half* A[4]; const __half* B[4];
    float* C[4]; const float* bias[4];
    float* C2[4]; const float* bias2[4];
    __half* Ch[4]; __half* Ch2[4];
};

#define HG_TILE  (128 * 80)
#define HG_STG   (2 * HG_TILE)
#define HG_SMEM  (4 * HG_STG)

template<bool RELU, int OUT>
__global__ void __launch_bounds__(256)
hg(SelH p, int K, int ldc)
{
    extern __shared__ __align__(16) char smraw[];
    const uint32_t sb = (uint32_t)__cvta_generic_to_shared(smraw);

    const int z   = blockIdx.z;
    const int tid = threadIdx.x, lane = tid & 31, wid = tid >> 5;
    const int warp_m = wid & 1, warp_n = wid >> 1;
    const long m0 = (long)blockIdx.y * 128, n0 = (long)blockIdx.x * 128;

    const __half* A  = p.A[z] + m0 * K;
    const __half* Bt = p.B[z] + n0 * K;
    const float* bias  = p.bias[z]  ? p.bias[z]  + n0 : nullptr;
    float*       C     = p.C[z]     ? p.C[z]     + m0 * ldc + n0 : nullptr;
    const float* bias2 = p.bias2[z] ? p.bias2[z] + n0 : nullptr;
    __half*      Ch    = p.Ch[z]    ? p.Ch[z]    + m0 * ldc + n0 : nullptr;
    __half*      Ch2   = p.Ch2[z]   ? p.Ch2[z]   + m0 * ldc + n0 : nullptr;

    float acc[4][4][4];
    #pragma unroll
    for (int i = 0; i < 4; i++)
        #pragma unroll
        for (int j = 0; j < 4; j++)
            #pragma unroll
            for (int l = 0; l < 4; l++) acc[i][j][l] = 0.f;

    const int ntile = K >> 5;

    auto issue = [&](int c) {
        const int st = c & 3;
        const int k0 = c << 5;
        const uint32_t ab = sb + (uint32_t)st * HG_STG;
        const uint32_t bb = ab + HG_TILE;
        #pragma unroll
        for (int i = 0; i < 2; i++) {
            int e = tid + i * 256;
            int row = e >> 2, sg = e & 3;
            cp16(ab + (uint32_t)(row * 80 + sg * 16),
                 &A[(long)row * K + k0 + sg * 8]);
        }
        #pragma unroll
        for (int i = 0; i < 2; i++) {
            int e = tid + i * 256;
            int row = e >> 2, sg = e & 3;
            cp16(bb + (uint32_t)(row * 80 + sg * 16),
                 &Bt[(long)row * K + k0 + sg * 8]);
        }
    };

    auto compute = [&](int st) {
        const uint32_t ab = sb + (uint32_t)st * HG_STG;
        const uint32_t bb = ab + HG_TILE;
        const int rw = lane & 7, grp = lane >> 3;
        const uint32_t acol = (uint32_t)((grp >> 1) * 16);
        const uint32_t rsel = (uint32_t)((grp & 1) * 8 + rw);
        #pragma unroll
        for (int kb = 0; kb < 2; kb++) {
            uint4 af[4];
            #pragma unroll
            for (int mt = 0; mt < 4; mt++)
                af[mt] = ldsm4(ab + (uint32_t)(warp_m * 64 + mt * 16 + rsel) * 80
                               + kb * 32 + acol);
            uint4 bq[2];
            #pragma unroll
            for (int nb = 0; nb < 2; nb++)
                bq[nb] = ldsm4(bb + (uint32_t)(warp_n * 32 + nb * 16 + rsel) * 80
                               + kb * 32 + acol);
            #pragma unroll
            for (int mt = 0; mt < 4; mt++)
                #pragma unroll
                for (int nt = 0; nt < 4; nt++) {
                    uint32_t b0 = (nt & 1) ? bq[nt >> 1].y : bq[nt >> 1].x;
                    uint32_t b1 = (nt & 1) ? bq[nt >> 1].w : bq[nt >> 1].z;
                    mma_f16(acc[mt][nt], af[mt], b0, b1);
                }
        }
    };

    issue(0); CP_COMMIT();
    if (ntile > 1) issue(1);
    CP_COMMIT();
    if (ntile > 2) issue(2);
    CP_COMMIT();
    for (int t = 0; t < ntile; t++) {
        CP_WAIT2();
        __syncthreads();
        if (t + 3 < ntile) issue(t + 3);
        CP_COMMIT();
        compute(t & 3);
    }

    // ---- epilogue ----
    #pragma unroll
    for (int mt = 0; mt < 4; mt++) {
        int rbase = warp_m * 64 + mt * 16 + (lane >> 2);
        #pragma unroll
        for (int nt = 0; nt < 4; nt++) {
            int cbase = warp_n * 32 + nt * 8 + (lane & 3) * 2;
            float* d = acc[mt][nt];
            float b0 = 0.f, b1 = 0.f;
            if (bias) { b0 = bias[cbase]; b1 = bias[cbase + 1]; }
            float v0 = d[0] + b0, v1 = d[1] + b1;
            float v2 = d[2] + b0, v3 = d[3] + b1;
            if (RELU) {
                v0 = fmaxf(v0, 0.f); v1 = fmaxf(v1, 0.f);
                v2 = fmaxf(v2, 0.f); v3 = fmaxf(v3, 0.f);
            }
            if (OUT == 2) {
                *(__half2*)&Ch[(long)rbase * ldc + cbase]       = __floats2half2_rn(v0, v1);
                *(__half2*)&Ch[(long)(rbase + 8) * ldc + cbase] = __floats2half2_rn(v2, v3);
                if (Ch2) {
                    float c0 = bias2[cbase], c1 = bias2[cbase + 1];
                    *(__half2*)&Ch2[(long)rbase * ldc + cbase] =
                        __floats2half2_rn(d[0] + c0, d[1] + c1);
                    *(__half2*)&Ch2[(long)(rbase + 8) * ldc + cbase] =
                        __floats2half2_rn(d[2] + c0, d[3] + c1);
                }
            } else {
                *(float2*)&C[(long)rbase * ldc + cbase]       = make_float2(v0, v1);
                *(float2*)&C[(long)(rbase + 8) * ldc + cbase] = make_float2(v2, v3);
            }
        }
    }
}

template<bool RELU, int OUT>
static void launch_hg(dim3 grid, const SelH& p, int K, int ldc)
{
    cudaFuncSetAttribute(hg<RELU, OUT>,
                         cudaFuncAttributeMaxDynamicSharedMemorySize, HG_SMEM);
    hg<RELU, OUT><<<grid, 256, HG_SMEM>>>(p, K, ldc);
}

// ---------------- input conversion passes ------------------------------------
__global__ void roundh_kernel(const float4* __restrict__ s0, __half* __restrict__ d0,
                              const float4* __restrict__ s1, __half* __restrict__ d1,
                              int n4) {
    const float4* s = blockIdx.y ? s1 : s0;
    __half*       d = blockIdx.y ? d1 : d0;
    for (int i = blockIdx.x * blockDim.x + threadIdx.x; i < n4;
         i += gridDim.x * blockDim.x) {
        float4 v = s[i];
        *(__half2*)&d[4 * i]     = __floats2half2_rn(v.x, v.y);
        *(__half2*)&d[4 * i + 2] = __floats2half2_rn(v.z, v.w);
    }
}

struct T7 { const float* in[7]; __half* out[7]; int K[7]; int N[7]; };

__global__ void txp_kernel(T7 t) {
    __shared__ float tb[32][33];
    const int z = blockIdx.z;
    const int K_ = t.K[z], N_ = t.N[z];
    const int n0 = blockIdx.x * 32, k0 = blockIdx.y * 32;
    if (n0 >= N_ || k0 >= K_) return;
    const int tx = threadIdx.x & 31, ty = threadIdx.x >> 5;
    #pragma unroll
    for (int i = 0; i < 32; i += 8)
        tb[ty + i][tx] = t.in[z][(long)(k0 + ty + i) * N_ + n0 + tx];
    __syncthreads();
    #pragma unroll
    for (int i = 0; i < 32; i += 8)
        t.out[z][(long)(n0 + ty + i) * K_ + k0 + tx] = __float2half_rn(tb[tx][ty + i]);
}

// ---------------- fused fp16 flash attention with rel-shift -------------------
// One CTA = 128 query rows of one (b,h). All MMAs m16n8k16 fp16, fp32 accum.
// smem (bytes): K[64]x144 | Vt[64]x144 | rr ring[192]x144 | P/E[128]x144
#define FLH_STB  144
#define FLH_KS   0
#define FLH_VT   9216
#define FLH_RR   18432
#define FLH_PB   46080
#define FLH_TOT  64512

__global__ void __launch_bounds__(256, 2)
flash_kernel(const __half* __restrict__ qwp, const __half* __restrict__ qrp,
             const __half* __restrict__ kp,  const __half* __restrict__ rp,
             const __half* __restrict__ vp,  __half* __restrict__ avph)
{
    extern __shared__ char smh[];
    __half* Vt = (__half*)(smh + FLH_VT);
    __half* Ph = (__half*)(smh + FLH_PB);
    const uint32_t base = (uint32_t)__cvta_generic_to_shared(smh);
    const uint32_t sK = base + FLH_KS;
    const uint32_t sV = base + FLH_VT;
    const uint32_t sR = base + FLH_RR;
    const uint32_t sP = base + FLH_PB;

    const int bid = blockIdx.x;
    const int it  = 7 - (bid >> 6);           // heavy blocks first
    const int bh  = bid & 63;
    const int b   = bh >> 4, h = bh & 15;
    const int i0  = it * 128;

    const int tid = threadIdx.x, lane = tid & 31, wid = tid >> 5;
    const int r0w = wid * 16;
    const int grp = lane >> 3, rw = lane & 7;
    const int r = lane >> 2, c = lane & 3;
    const uint32_t rsel = (uint32_t)((grp & 1) * 8 + rw);
    const uint32_t acol = (uint32_t)((grp >> 1) * 16);

    const long qbase  = ((long)(b * Sq + i0)) * Dm + h * 64;
    const long kvbase = ((long)b * Sq) * Dm + h * 64;

    // ---- stage Q tiles (qw -> rr area, qr -> P area); extract fragments ----
    for (int e = tid; e < 128 * 8; e += 256) {
        int row = e >> 3, sg = e & 7;
        cp16(sR + (uint32_t)(row * FLH_STB + sg * 16), &qwp[qbase + (long)row * Dm + sg * 8]);
        cp16(sP + (uint32_t)(row * FLH_STB + sg * 16), &qrp[qbase + (long)row * Dm + sg * 8]);
    }
    CP_COMMIT(); CP_WAIT_ALL(); __syncthreads();
    uint4 qwf[4], qrf[4];
    #pragma unroll
    for (int kb = 0; kb < 4; kb++) {
        uint32_t off = (uint32_t)((r0w + rsel) * FLH_STB) + kb * 32 + acol;
        qwf[kb] = ldsm4(sR + off);
        qrf[kb] = ldsm4(sP + off);
    }

    float m0v = -1e30f, m1v = -1e30f, l0v = 0.f, l1v = 0.f;
    float o_[8][4];
    #pragma unroll
    for (int i = 0; i < 8; i++)
        #pragma unroll
        for (int j = 0; j < 4; j++) o_[i][j] = 0.f;

    const int njt = (i0 >> 6) + 2;
    for (int jt = 0; jt < njt; jt++) {
        const int j0 = jt * 64;
        const int l0 = Sq - 128 + j0 - i0;    // rr window base (64-aligned, >= 0)
        __syncthreads();                       // prev-tile smem reads done

        // K tile
        for (int e = tid; e < 64 * 8; e += 256) {
            int row = e >> 3, sg = e & 7;
            cp16(sK + (uint32_t)(row * FLH_STB + sg * 16),
                 &kp[kvbase + (long)(j0 + row) * Dm + sg * 8]);
        }
        // rr ring: first tile 192 rows; later only 64 new
        {
            int rlo = (jt == 0) ? 0 : 128;
            for (int e = tid + rlo * 8; e < 192 * 8; e += 256) {
                int row = e >> 3, sg = e & 7;
                int l = l0 + row;
                int slot = (((l >> 6) % 3) << 6) + (l & 63);
                int lr = l > Sq - 1 ? Sq - 1 : l;
                cp16(sR + (uint32_t)(slot * FLH_STB + sg * 16),
                     &rp[kvbase + (long)lr * Dm + sg * 8]);
            }
        }
        CP_COMMIT();
        // V tile: LDG + transposed half stores -> Vt[d][j]
        {
            int jj = tid >> 2, db = (tid & 3) << 4;
            const __half* vrow = &vp[kvbase + (long)(j0 + jj) * Dm + db];
            uint4 t0 = *(const uint4*)vrow;
            uint4 t1 = *(const uint4*)(vrow + 8);
            const __half* hsrc0 = (const __half*)&t0;
            const __half* hsrc1 = (const __half*)&t1;
            #pragma unroll
            for (int u = 0; u < 8; u++) Vt[(db + u) * 72 + jj]     = hsrc0[u];
            #pragma unroll
            for (int u = 0; u < 8; u++) Vt[(db + 8 + u) * 72 + jj] = hsrc1[u];
        }
        CP_WAIT_ALL(); __syncthreads();

        // ---- E band MMA: E[ii][d_win] -> half scatter (ii, jj=d-127+ii) ----
        {
            int dlo = 105 - r0w; if (dlo < 0) dlo = 0; dlo &= ~7;
            int dhi = (190 - r0w) & ~7;
            for (int d0 = dlo; d0 <= dhi; d0 += 16) {
                bool has2 = (d0 + 8 <= dhi);
                float e0[4] = {0.f,0.f,0.f,0.f}, e1[4] = {0.f,0.f,0.f,0.f};
                int lb = l0 + d0 + (grp & 1) * 8;          // 8-aligned in segment
                int slotb = (((lb >> 6) % 3) << 6) + (lb & 63);
                #pragma unroll
                for (int kb = 0; kb < 4; kb++) {
                    uint4 bf = ldsm4(sR + (uint32_t)((slotb + rw) * FLH_STB)
                                     + kb * 32 + acol);
                    // x = d0+0-7/k0-7, y = d0+8-15/k0-7, z = d0+0-7/k8-15, w = d0+8-15/k8-15
                    mma_f16(e0, qrf[kb], bf.x, bf.z);
                    if (has2) mma_f16(e1, qrf[kb], bf.y, bf.w);
                }
                int ii0 = r0w + r, ii1 = ii0 + 8;
                int d = d0 + 2 * c;
                int ja = d - 127 + ii0, jb = d - 127 + ii1;
                if (ja     >= 0 && ja     < 64) Ph[ii0 * 72 + ja    ] = __float2half_rn(e0[0]);
                if (ja + 1 >= 0 && ja + 1 < 64) Ph[ii0 * 72 + ja + 1] = __float2half_rn(e0[1]);
                if (jb     >= 0 && jb     < 64) Ph[ii1 * 72 + jb    ] = __float2half_rn(e0[2]);
                if (jb + 1 >= 0 && jb + 1 < 64) Ph[ii1 * 72 + jb + 1] = __float2half_rn(e0[3]);
                if (has2) {
                    int ja2 = ja + 8, jb2 = jb + 8;
                    if (ja2     >= 0 && ja2     < 64) Ph[ii0 * 72 + ja2    ] = __float2half_rn(e1[0]);
                    if (ja2 + 1 >= 0 && ja2 + 1 < 64) Ph[ii0 * 72 + ja2 + 1] = __float2half_rn(e1[1]);
                    if (jb2     >= 0 && jb2     < 64) Ph[ii1 * 72 + jb2    ] = __float2half_rn(e1[2]);
                    if (jb2 + 1 >= 0 && jb2 + 1 < 64) Ph[ii1 * 72 + jb2 + 1] = __float2half_rn(e1[3]);
                }
            }
        }
        __syncwarp();   // band written by this warp's lanes, read below

        // ---- ac MMA (fp16) ----
        float s_[8][4];
        #pragma unroll
        for (int i = 0; i < 8; i++)
            #pragma unroll
            for (int j = 0; j < 4; j++) s_[i][j] = 0.f;
        #pragma unroll
        for (int kb = 0; kb < 4; kb++) {
            #pragma unroll
            for (int nb = 0; nb < 4; nb++) {
                uint4 bq = ldsm4(sK + (uint32_t)((nb * 16 + rsel) * FLH_STB)
                                 + kb * 32 + acol);
                // x = n0-7/k0-7, y = n8-15/k0-7, z = n0-7/k8-15, w = n8-15/k8-15
                mma_f16(s_[2 * nb],     qwf[kb], bq.x, bq.z);
                mma_f16(s_[2 * nb + 1], qwf[kb], bq.y, bq.w);
            }
        }

        // ---- S = (ac + E)*scale, mask, online softmax ----
        const int gi0 = i0 + r0w + r, gi1 = gi0 + 8;
        float mx0 = -1e30f, mx1 = -1e30f;
        #pragma unroll
        for (int nt = 0; nt < 8; nt++) {
            int jj = nt * 8 + 2 * c, jg = j0 + jj;
            float e00 = __half2float(Ph[(r0w + r) * 72 + jj]);
            float e01 = __half2float(Ph[(r0w + r) * 72 + jj + 1]);
            float e10 = __half2float(Ph[(r0w + r + 8) * 72 + jj]);
            float e11 = __half2float(Ph[(r0w + r + 8) * 72 + jj + 1]);
            s_[nt][0] = (jg     <= gi0) ? (s_[nt][0] + e00) * 0.125f : -1e30f;
            s_[nt][1] = (jg + 1 <= gi0) ? (s_[nt][1] + e01) * 0.125f : -1e30f;
            s_[nt][2] = (jg     <= gi1) ? (s_[nt][2] + e10) * 0.125f : -1e30f;
            s_[nt][3] = (jg + 1 <= gi1) ? (s_[nt][3] + e11) * 0.125f : -1e30f;
            mx0 = fmaxf(mx0, fmaxf(s_[nt][0], s_[nt][1]));
            mx1 = fmaxf(mx1, fmaxf(s_[nt][2], s_[nt][3]));
        }
        mx0 = fmaxf(mx0, __shfl_xor_sync(0xffffffffu, mx0, 1));
        mx0 = fmaxf(mx0, __shfl_xor_sync(0xffffffffu, mx0, 2));
        mx1 = fmaxf(mx1, __shfl_xor_sync(0xffffffffu, mx1, 1));
        mx1 = fmaxf(mx1, __shfl_xor_sync(0xffffffffu, mx1, 2));
        float mn0 = fmaxf(m0v, mx0), mn1 = fmaxf(m1v, mx1);
        float a0 = __expf(m0v - mn0), a1 = __expf(m1v - mn1);
        float sum0 = 0.f, sum1 = 0.f;
        #pragma unroll
        for (int nt = 0; nt < 8; nt++) {
            int jj = nt * 8 + 2 * c;
            float p00 = __expf(s_[nt][0] - mn0), p01 = __expf(s_[nt][1] - mn0);
            float p10 = __expf(s_[nt][2] - mn1), p11 = __expf(s_[nt][3] - mn1);
            sum0 += p00 + p01; sum1 += p10 + p11;
            *(__half2*)&Ph[(r0w + r) * 72 + jj]     = __floats2half2_rn(p00, p01);
            *(__half2*)&Ph[(r0w + r + 8) * 72 + jj] = __floats2half2_rn(p10, p11);
        }
        sum0 += __shfl_xor_sync(0xffffffffu, sum0, 1);
        sum0 += __shfl_xor_sync(0xffffffffu, sum0, 2);
        sum1 += __shfl_xor_sync(0xffffffffu, sum1, 1);
        sum1 += __shfl_xor_sync(0xffffffffu, sum1, 2);
        l0v = l0v * a0 + sum0; l1v = l1v * a1 + sum1;
        m0v = mn0; m1v = mn1;
        #pragma unroll
        for (int dt = 0; dt < 8; dt++) {
            o_[dt][0] *= a0; o_[dt][1] *= a0;
            o_[dt][2] *= a1; o_[dt][3] *= a1;
        }
        __syncwarp();   // P written by this warp, read via ldmatrix below

        // ---- PV: O += P @ V (fp16) ----
        // NOTE: P rows here live at stride 72 halves = 144 B = FLH_STB; the
        // ldmatrix below uses the same stride as the staging layout.
        #pragma unroll
        for (int kb = 0; kb < 4; kb++) {
            uint4 af = ldsm4(sP + (uint32_t)((r0w + rsel) * FLH_STB) + kb * 32 + acol);
            #pragma unroll
            for (int nb = 0; nb < 4; nb++) {
                uint4 bq = ldsm4(sV + (uint32_t)((nb * 16 + rsel) * FLH_STB)
                                 + kb * 32 + acol);
                mma_f16(o_[2 * nb],     af, bq.x, bq.z);
                mma_f16(o_[2 * nb + 1], af, bq.y, bq.w);
            }
        }
    }

    // ---- epilogue: O / l, fp16 (feeds Wo hgemm) ----
    float i0v = 1.f / l0v, i1v = 1.f / l1v;
    long ob0 = ((long)(b * Sq + i0 + r0w + r)) * Dm + h * 64;
    long ob1 = ob0 + 8L * Dm;
    #pragma unroll
    for (int dt = 0; dt < 8; dt++) {
        int d = dt * 8 + 2 * c;
        *(__half2*)&avph[ob0 + d] = __floats2half2_rn(o_[dt][0] * i0v, o_[dt][1] * i0v);
        *(__half2*)&avph[ob1 + d] = __floats2half2_rn(o_[dt][2] * i1v, o_[dt][3] * i1v);
    }
}

// ---------------- reductions / LN --------------------------------------------
__device__ __forceinline__ float warpSum(float v) {
    #pragma unroll
    for (int o = 16; o > 0; o >>= 1) v += __shfl_xor_sync(0xffffffffu, v, o);
    return v;
}
__device__ float blockSum(float v) {
    __shared__ float red[8];
    __syncthreads();
    int lane = threadIdx.x & 31, wid = threadIdx.x >> 5;
    v = warpSum(v);
    if (lane == 0) red[wid] = v;
    __syncthreads();
    if (wid == 0) {
        float t = (lane < 8) ? red[lane] : 0.f;
        t = warpSum(t);
        if (lane == 0) red[0] = t;
    }
    __syncthreads();
    return red[0];
}

__global__ void ln_kernel(const float* __restrict__ a, const float* __restrict__ b,
                          const float* __restrict__ gam, const float* __restrict__ bet,
                          float* __restrict__ out, __half* __restrict__ out_h)
{
    const long row = blockIdx.x;
    const long base = row * Dm;
    __shared__ float sbuf[Dm];
    const int tid = threadIdx.x;

    float ls = 0.f;
    for (int j = tid; j < Dm; j += blockDim.x) {
        float x = a[base + j] + b[base + j];
        sbuf[j] = x;
        ls += x;
    }
    float mu = blockSum(ls) * (1.f / Dm);

    float lv = 0.f;
    for (int j = tid; j < Dm; j += blockDim.x) {
        float d = sbuf[j] - mu;
        lv += d * d;
    }
    float var = blockSum(lv) * (1.f / Dm);
    float inv = rsqrtf(var + EPS);

    for (int j = tid; j < Dm; j += blockDim.x) {
        float y = (sbuf[j] - mu) * inv * gam[j] + bet[j];
        out[base + j] = y;
        if (out_h) out_h[base + j] = __float2half_rn(y);
    }
}

// ---------------- launch ----------------------------------------------------
extern "C" void kernel_launch(void* const* d_in, const int* in_sizes, int n_in,
                              void* d_out, int out_size)
{
    const float* w      = (const float*)d_in[0];
    const float* r      = (const float*)d_in[1];
    const float* w_bias = (const float*)d_in[2];
    const float* r_bias = (const float*)d_in[3];
    const float* b1     = (const float*)d_in[12];
    const float* b2     = (const float*)d_in[14];
    const float* ln1g   = (const float*)d_in[9];
    const float* ln1b   = (const float*)d_in[10];
    const float* ln2g   = (const float*)d_in[15];
    const float* ln2b   = (const float*)d_in[16];
    float* out = (float*)d_out;

    float *ao, *x, *f;
    __half *qwh, *qrh, *kh, *vh, *rrh, *avh, *xh, *hh, *wh, *rh;
    __half *Wqt, *Wkt, *Wvt, *Wrt, *Wot, *W1t, *W2t;
    cudaGetSymbolAddress((void**)&ao,  g_ao);
    cudaGetSymbolAddress((void**)&x,   g_x);
    cudaGetSymbolAddress((void**)&f,   g_f);
    cudaGetSymbolAddress((void**)&qwh, g_qwh);
    cudaGetSymbolAddress((void**)&qrh, g_qrh);
    cudaGetSymbolAddress((void**)&kh,  g_kh);
    cudaGetSymbolAddress((void**)&vh,  g_vh);
    cudaGetSymbolAddress((void**)&rrh, g_rrh);
    cudaGetSymbolAddress((void**)&avh, g_avh);
    cudaGetSymbolAddress((void**)&xh,  g_xh);
    cudaGetSymbolAddress((void**)&hh,  g_hh);
    cudaGetSymbolAddress((void**)&wh,  g_wh);
    cudaGetSymbolAddress((void**)&rh,  g_rh);
    cudaGetSymbolAddress((void**)&Wqt, g_Wqt);
    cudaGetSymbolAddress((void**)&Wkt, g_Wkt);
    cudaGetSymbolAddress((void**)&Wvt, g_Wvt);
    cudaGetSymbolAddress((void**)&Wrt, g_Wrt);
    cudaGetSymbolAddress((void**)&Wot, g_Wot);
    cudaGetSymbolAddress((void**)&W1t, g_W1t);
    cudaGetSymbolAddress((void**)&W2t, g_W2t);

    const int M = Bq * Sq;

    // 0a) fp16 conversion of activations w, r
    roundh_kernel<<<dim3(512, 2), 256>>>((const float4*)w, wh,
                                         (const float4*)r, rh,
                                         Bq * Sq * Dm / 4);

    // 0b) transpose + fp16 of the 7 weights
    {
        T7 t{};
        const float* ins[7] = { (const float*)d_in[4], (const float*)d_in[5],
                                (const float*)d_in[6], (const float*)d_in[7],
                                (const float*)d_in[8], (const float*)d_in[11],
                                (const float*)d_in[13] };
        __half* outs[7] = { Wqt, Wkt, Wvt, Wrt, Wot, W1t, W2t };
        int Ks[7] = { Dm, Dm, Dm, Dm, Dm, Dm, DIf };
        int Ns[7] = { Dm, Dm, Dm, Dm, Dm, DIf, Dm };
        for (int i = 0; i < 7; i++) { t.in[i]=ins[i]; t.out[i]=outs[i]; t.K[i]=Ks[i]; t.N[i]=Ns[i]; }
        txp_kernel<<<dim3(128, 128, 7), 256>>>(t);
    }

    // 1) four projections -> fp16 outputs; q-biases fused (qw & qr dual)
    {
        SelH p{};
        p.A[0] = wh;  p.A[1] = wh;  p.A[2] = wh;  p.A[3] = rh;
        p.B[0] = Wqt; p.B[1] = Wkt; p.B[2] = Wvt; p.B[3] = Wrt;
        p.Ch[0] = qwh; p.Ch[1] = kh; p.Ch[2] = vh; p.Ch[3] = rrh;
        p.bias[0]  = w_bias;
        p.Ch2[0]   = qrh;
        p.bias2[0] = r_bias;
        launch_hg<false, 2>(dim3(Dm / 128, M / 128, 4), p, Dm, Dm);
    }

    // 2) fused fp16 flash attention
    cudaFuncSetAttribute(flash_kernel,
                         cudaFuncAttributeMaxDynamicSharedMemorySize, FLH_TOT);
    flash_kernel<<<512, 256, FLH_TOT>>>(qwh, qrh, kh, rrh, vh, avh);

    // 3) attn_out = av @ Wo (fp32 out)
    {
        SelH p{};
        p.A[0] = avh; p.B[0] = Wot; p.C[0] = ao;
        launch_hg<false, 0>(dim3(Dm / 128, M / 128, 1), p, Dm, Dm);
    }

    // 4) x = LN(w + attn_out); xh = fp16(x)
    ln_kernel<<<M, 256>>>(w, ao, ln1g, ln1b, x, xh);

    // 5) FFN: hh = fp16(relu(x @ W1 + b1)); f = hh @ W2 + b2
    {
        SelH p{};
        p.A[0] = xh; p.B[0] = W1t; p.bias[0] = b1; p.Ch[0] = hh;
        launch_hg<true, 2>(dim3(DIf / 128, M / 128, 1), p, Dm, DIf);
    }
    {
        SelH p{};
        p.A[0] = hh; p.B[0] = W2t; p.bias[0] = b2; p.C[0] = f;
        launch_hg<false, 0>(dim3(Dm / 128, M / 128, 1), p, DIf, Dm);
    }

    // 6) out = LN(x + f)
    ln_kernel<<<M, 256>>>(x, f, ln2g, ln2b, out, nullptr);
}